// round 1
// baseline (speedup 1.0000x reference)
#include <cuda_runtime.h>
#include <cuda_bf16.h>

#define T_LEN   4000
#define THREADS 256
#define EPT     16      // elements per thread; 256*16 = 4096 >= 4000; 4000/16 = 250 exact
#define NV4     1000    // float4 per row

__global__ __launch_bounds__(THREADS)
void pcen_kernel(const float* __restrict__ x, float* __restrict__ out)
{
    __shared__ float4 s4[THREADS * EPT / 4];   // 4096 floats = 16 KB
    __shared__ float warpA[8], warpB[8];
    float* s = reinterpret_cast<float*>(s4);

    const float a     = 0.975f;     // 1 - S
    const float S_    = 0.025f;
    const float ALPHA = 0.98f;
    const float DELTA = 2.0f;
    const float EPSf  = 1e-6f;
    const float DR    = 1.41421356237309515f;  // DELTA^0.5

    const int row = blockIdx.x;
    const int tid = threadIdx.x;
    const float4* __restrict__ xr4 = reinterpret_cast<const float4*>(x + (size_t)row * T_LEN);
    float4* __restrict__       or4 = reinterpret_cast<float4*>(out + (size_t)row * T_LEN);

    // ---- coalesced load into smem ----
    #pragma unroll
    for (int q = 0; q < 4; q++) {
        int i = tid + q * THREADS;
        if (i < NV4) s4[i] = xr4[i];
    }
    if (tid < (THREADS * EPT - T_LEN)) s[T_LEN + tid] = 0.0f;   // zero pad tail
    __syncthreads();

    // ---- per-thread contiguous chunk ----
    float v[EPT];
    float4* myc = s4 + tid * (EPT / 4);
    #pragma unroll
    for (int q = 0; q < 4; q++) {
        float4 t4 = myc[q];
        v[4*q+0] = t4.x; v[4*q+1] = t4.y; v[4*q+2] = t4.z; v[4*q+3] = t4.w;
    }

    // ---- local serial scan (zero carry-in) ----
    // b[0] = x[0] (init cond), b[t] = S*x[t] for t >= 1
    float sm_local[EPT];
    float h = 0.0f;
    #pragma unroll
    for (int j = 0; j < EPT; j++) {
        float b = (tid == 0 && j == 0) ? v[0] : S_ * v[j];
        h = fmaf(a, h, b);
        sm_local[j] = h;
    }

    // ---- block scan of (A = a^16, B = h) ----
    float t2 = a * a, t4 = t2 * t2, t8 = t4 * t4;
    const float A16 = t8 * t8;

    float A = A16, B = h;
    const int lane = tid & 31, warp = tid >> 5;
    #pragma unroll
    for (int off = 1; off < 32; off <<= 1) {
        float Ap = __shfl_up_sync(0xFFFFFFFFu, A, off);
        float Bp = __shfl_up_sync(0xFFFFFFFFu, B, off);
        if (lane >= off) { B = fmaf(A, Bp, B); A *= Ap; }
    }
    if (lane == 31) { warpA[warp] = A; warpB[warp] = B; }
    __syncthreads();

    // exclusive-within-warp
    float eA = __shfl_up_sync(0xFFFFFFFFu, A, 1);
    float eB = __shfl_up_sync(0xFFFFFFFFu, B, 1);
    if (lane == 0) { eA = 1.0f; eB = 0.0f; }

    // exclusive warp-prefix (8 warps, serial broadcast loop)
    float wB = 0.0f;
    #pragma unroll
    for (int w = 0; w < 8; w++) {
        if (w < warp) wB = fmaf(warpA[w], wB, warpB[w]);
    }
    // carry-in for this thread: apply thread-exclusive on top of warp prefix
    const float C = fmaf(eA, wB, eB);

    // ---- apply carry + pointwise PCEN ----
    float ap = a;
    #pragma unroll
    for (int j = 0; j < EPT; j++) {
        float sm = fmaf(ap, C, sm_local[j]);
        ap *= a;
        float p  = __powf(sm + EPSf, -ALPHA);            // 1/(sm+eps)^alpha : lg2+mul+ex2
        v[j] = sqrtf(fmaf(v[j], p, DELTA)) - DR;
    }

    // own chunk only -> no race; sync before full coalesced read-out
    #pragma unroll
    for (int q = 0; q < 4; q++)
        myc[q] = make_float4(v[4*q+0], v[4*q+1], v[4*q+2], v[4*q+3]);
    __syncthreads();

    #pragma unroll
    for (int q = 0; q < 4; q++) {
        int i = tid + q * THREADS;
        if (i < NV4) or4[i] = s4[i];
    }
}

extern "C" void kernel_launch(void* const* d_in, const int* in_sizes, int n_in,
                              void* d_out, int out_size)
{
    const float* x = (const float*)d_in[0];
    float* out = (float*)d_out;
    int rows = in_sizes[0] / T_LEN;   // 64*128 = 8192
    pcen_kernel<<<rows, THREADS>>>(x, out);
}

// round 3
// speedup vs baseline: 1.5319x; 1.5319x over previous
#include <cuda_runtime.h>
#include <cuda_bf16.h>

#define T_LEN   4000
#define THREADS 256
#define EPT     16      // 256*16 = 4096 >= 4000
#define NV4     1000    // float4 per row

// XOR swizzle on float4 index: kills 4-way bank conflicts on the transpose access.
__device__ __forceinline__ int SW(int i) { return i ^ ((i >> 2) & 7); }

__device__ __forceinline__ float fsqrt_approx(float u) {
    float r;
    asm("sqrt.approx.f32 %0, %1;" : "=f"(r) : "f"(u));
    return r;
}
__device__ __forceinline__ float flg2(float u) {
    float r;
    asm("lg2.approx.f32 %0, %1;" : "=f"(r) : "f"(u));
    return r;
}
__device__ __forceinline__ float fex2(float u) {
    float r;
    asm("ex2.approx.f32 %0, %1;" : "=f"(r) : "f"(u));
    return r;
}

__global__ __launch_bounds__(THREADS)
void pcen_kernel(const float* __restrict__ x, float* __restrict__ out)
{
    __shared__ float4 s4[THREADS * EPT / 4];   // 1024 float4 = 16 KB
    __shared__ float warpA[8], warpB[8];

    const float a      = 0.975f;     // 1 - S
    const float S_     = 0.025f;
    const float NALPHA = -0.98f;
    const float DELTA  = 2.0f;
    const float EPSf   = 1e-6f;
    const float DR     = 1.41421356237309515f;  // sqrt(2)

    const int row = blockIdx.x;
    const int tid = threadIdx.x;
    const float4* __restrict__ xr4 = reinterpret_cast<const float4*>(x + (size_t)row * T_LEN);
    float4* __restrict__       or4 = reinterpret_cast<float4*>(out + (size_t)row * T_LEN);

    // ---- coalesced load into swizzled smem ----
    #pragma unroll
    for (int q = 0; q < 4; q++) {
        int i = tid + q * THREADS;
        if (i < NV4) s4[SW(i)] = xr4[i];
    }
    if (tid < 24) s4[SW(NV4 + tid)] = make_float4(0.f, 0.f, 0.f, 0.f);  // zero tail
    __syncthreads();

    // ---- per-thread contiguous chunk (conflict-free via swizzle) ----
    float v[EPT];
    #pragma unroll
    for (int q = 0; q < 4; q++) {
        float4 t4 = s4[SW(tid * 4 + q)];
        v[4*q+0] = t4.x; v[4*q+1] = t4.y; v[4*q+2] = t4.z; v[4*q+3] = t4.w;
    }

    // ---- pass 1: local recurrence with zero carry-in (only final h needed) ----
    // b[0] = x[0] (init), b[t] = S*x[t] for t >= 1
    float h = 0.0f;
    #pragma unroll
    for (int j = 0; j < EPT; j++) {
        float b = (tid == 0 && j == 0) ? v[0] : S_ * v[j];
        h = fmaf(a, h, b);
    }

    // ---- block scan of pairs (A = a^16, B = h) ----
    float t2 = a * a, t4 = t2 * t2, t8 = t4 * t4;
    const float A16 = t8 * t8;

    float A = A16, B = h;
    const int lane = tid & 31, warp = tid >> 5;
    #pragma unroll
    for (int off = 1; off < 32; off <<= 1) {
        float Ap = __shfl_up_sync(0xFFFFFFFFu, A, off);
        float Bp = __shfl_up_sync(0xFFFFFFFFu, B, off);
        if (lane >= off) { B = fmaf(A, Bp, B); A *= Ap; }
    }
    if (lane == 31) { warpA[warp] = A; warpB[warp] = B; }
    __syncthreads();

    // thread-exclusive within warp
    float eA = __shfl_up_sync(0xFFFFFFFFu, A, 1);
    float eB = __shfl_up_sync(0xFFFFFFFFu, B, 1);
    if (lane == 0) { eA = 1.0f; eB = 0.0f; }

    // exclusive warp-level prefix (8 warps, tiny serial loop)
    float wB = 0.0f;
    #pragma unroll
    for (int w = 0; w < 8; w++) {
        if (w < warp) wB = fmaf(warpA[w], wB, warpB[w]);
    }
    const float C = fmaf(eA, wB, eB);   // inclusive smooth just before this chunk

    // ---- pass 2: re-run recurrence seeded with carry + pointwise PCEN ----
    float sm = C;
    #pragma unroll
    for (int j = 0; j < EPT; j++) {
        float b = (tid == 0 && j == 0) ? v[0] : S_ * v[j];
        sm = fmaf(a, sm, b);
        float p = fex2(NALPHA * flg2(sm + EPSf));   // (sm+eps)^-0.98
        v[j] = fsqrt_approx(fmaf(v[j], p, DELTA)) - DR;
    }

    // ---- write own chunk back through swizzled smem ----
    #pragma unroll
    for (int q = 0; q < 4; q++)
        s4[SW(tid * 4 + q)] = make_float4(v[4*q+0], v[4*q+1], v[4*q+2], v[4*q+3]);
    __syncthreads();

    #pragma unroll
    for (int q = 0; q < 4; q++) {
        int i = tid + q * THREADS;
        if (i < NV4) or4[i] = s4[SW(i)];
    }
}

extern "C" void kernel_launch(void* const* d_in, const int* in_sizes, int n_in,
                              void* d_out, int out_size)
{
    const float* x = (const float*)d_in[0];
    float* out = (float*)d_out;
    int rows = in_sizes[0] / T_LEN;   // 8192
    pcen_kernel<<<rows, THREADS>>>(x, out);
}

// round 4
// speedup vs baseline: 1.6697x; 1.0900x over previous
#include <cuda_runtime.h>
#include <cuda_bf16.h>

#define T_LEN   4000
#define THREADS 256
#define EPT     16      // 256*16 = 4096 >= 4000
#define NV4     1000    // float4 per row

// XOR swizzle on float4 index: conflict-free transpose access.
__device__ __forceinline__ int SW(int i) { return i ^ ((i >> 2) & 7); }

__device__ __forceinline__ float fsqrt_approx(float u) {
    float r; asm("sqrt.approx.f32 %0, %1;" : "=f"(r) : "f"(u)); return r;
}
__device__ __forceinline__ float flg2(float u) {
    float r; asm("lg2.approx.f32 %0, %1;" : "=f"(r) : "f"(u)); return r;
}
__device__ __forceinline__ float fex2(float u) {
    float r; asm("ex2.approx.f32 %0, %1;" : "=f"(r) : "f"(u)); return r;
}

__global__ __launch_bounds__(THREADS, 8)   // force <=32 regs -> 64 warps/SM
void pcen_kernel(const float* __restrict__ x, float* __restrict__ out)
{
    __shared__ float4 s4[THREADS * EPT / 4];   // 1024 float4 = 16 KB
    __shared__ float warpA[8], warpB[8];

    const float a      = 0.975f;     // 1 - S
    const float S_     = 0.025f;
    const float NALPHA = -0.98f;
    const float DELTA  = 2.0f;
    const float EPSf   = 1e-6f;
    const float DR     = 1.41421356237309515f;  // sqrt(2)

    const int row = blockIdx.x;
    const int tid = threadIdx.x;
    const float4* __restrict__ xr4 = reinterpret_cast<const float4*>(x + (size_t)row * T_LEN);
    float4* __restrict__       or4 = reinterpret_cast<float4*>(out + (size_t)row * T_LEN);

    // ---- coalesced load into swizzled smem ----
    #pragma unroll
    for (int q = 0; q < 4; q++) {
        int i = tid + q * THREADS;
        if (i < NV4) s4[SW(i)] = xr4[i];
    }
    if (tid < 24) s4[SW(NV4 + tid)] = make_float4(0.f, 0.f, 0.f, 0.f);  // zero tail
    __syncthreads();

    // ---- pass 1: local recurrence, zero carry-in; keep only final h ----
    // b[0] = x[0] (init), b[t] = S*x[t] for t >= 1
    float h = 0.0f;
    #pragma unroll
    for (int q = 0; q < 4; q++) {
        float4 t4 = s4[SW(tid * 4 + q)];
        float b0 = (tid == 0 && q == 0) ? t4.x : S_ * t4.x;
        h = fmaf(a, h, b0);
        h = fmaf(a, h, S_ * t4.y);
        h = fmaf(a, h, S_ * t4.z);
        h = fmaf(a, h, S_ * t4.w);
    }

    // ---- block scan of pairs (A = a^16, B = h) ----
    float p2 = a * a, p4 = p2 * p2, p8 = p4 * p4;
    const float A16 = p8 * p8;

    float A = A16, B = h;
    const int lane = tid & 31, warp = tid >> 5;
    #pragma unroll
    for (int off = 1; off < 32; off <<= 1) {
        float Ap = __shfl_up_sync(0xFFFFFFFFu, A, off);
        float Bp = __shfl_up_sync(0xFFFFFFFFu, B, off);
        if (lane >= off) { B = fmaf(A, Bp, B); A *= Ap; }
    }
    if (lane == 31) { warpA[warp] = A; warpB[warp] = B; }
    __syncthreads();

    // thread-exclusive within warp
    float eA = __shfl_up_sync(0xFFFFFFFFu, A, 1);
    float eB = __shfl_up_sync(0xFFFFFFFFu, B, 1);
    if (lane == 0) { eA = 1.0f; eB = 0.0f; }

    // exclusive warp-level prefix (8 warps, tiny serial loop)
    float wB = 0.0f;
    #pragma unroll
    for (int w = 0; w < 8; w++) {
        if (w < warp) wB = fmaf(warpA[w], wB, warpB[w]);
    }
    float sm = fmaf(eA, wB, eB);   // inclusive smooth just before this chunk

    // ---- pass 2: re-read chunk, seeded recurrence + pointwise PCEN, write in place ----
    #pragma unroll
    for (int q = 0; q < 4; q++) {
        float4 t4 = s4[SW(tid * 4 + q)];

        float b0 = (tid == 0 && q == 0) ? t4.x : S_ * t4.x;
        sm = fmaf(a, sm, b0);
        float r0 = fsqrt_approx(fmaf(t4.x, fex2(NALPHA * flg2(sm + EPSf)), DELTA)) - DR;

        sm = fmaf(a, sm, S_ * t4.y);
        float r1 = fsqrt_approx(fmaf(t4.y, fex2(NALPHA * flg2(sm + EPSf)), DELTA)) - DR;

        sm = fmaf(a, sm, S_ * t4.z);
        float r2 = fsqrt_approx(fmaf(t4.z, fex2(NALPHA * flg2(sm + EPSf)), DELTA)) - DR;

        sm = fmaf(a, sm, S_ * t4.w);
        float r3 = fsqrt_approx(fmaf(t4.w, fex2(NALPHA * flg2(sm + EPSf)), DELTA)) - DR;

        s4[SW(tid * 4 + q)] = make_float4(r0, r1, r2, r3);
    }
    __syncthreads();

    // ---- coalesced store ----
    #pragma unroll
    for (int q = 0; q < 4; q++) {
        int i = tid + q * THREADS;
        if (i < NV4) or4[i] = s4[SW(i)];
    }
}

extern "C" void kernel_launch(void* const* d_in, const int* in_sizes, int n_in,
                              void* d_out, int out_size)
{
    const float* x = (const float*)d_in[0];
    float* out = (float*)d_out;
    int rows = in_sizes[0] / T_LEN;   // 8192
    pcen_kernel<<<rows, THREADS>>>(x, out);
}

// round 5
// speedup vs baseline: 1.7368x; 1.0402x over previous
#include <cuda_runtime.h>
#include <cuda_bf16.h>

#define T_LEN   4000
#define THREADS 256
#define NSEG    4       // 4 segments x 1024 elements = 4096 >= 4000

__device__ __forceinline__ float fsqrt_approx(float u) {
    float r; asm("sqrt.approx.f32 %0, %1;" : "=f"(r) : "f"(u)); return r;
}
__device__ __forceinline__ float flg2(float u) {
    float r; asm("lg2.approx.f32 %0, %1;" : "=f"(r) : "f"(u)); return r;
}
__device__ __forceinline__ float fex2(float u) {
    float r; asm("ex2.approx.f32 %0, %1;" : "=f"(r) : "f"(u)); return r;
}

__global__ __launch_bounds__(THREADS, 6)
void pcen_kernel(const float* __restrict__ x, float* __restrict__ out)
{
    __shared__ float sT[32];   // (segment, warp) chunk totals
    __shared__ float sC[32];   // exclusive carries per (segment, warp) chunk

    const float a      = 0.975f;     // 1 - S
    const float S_     = 0.025f;
    const float NALPHA = -0.98f;
    const float DELTA  = 2.0f;
    const float EPSf   = 1e-6f;
    const float DR     = 1.41421356237309515f;  // sqrt(2)

    const int tid  = threadIdx.x;
    const int lane = tid & 31, warp = tid >> 5;
    const int row  = blockIdx.x;
    const float* __restrict__ xr   = x   + (size_t)row * T_LEN;
    float* __restrict__       orow = out + (size_t)row * T_LEN;

    // exact powers of a by squaring
    const float a2 = a*a, a4 = a2*a2, a8 = a4*a4, a16 = a8*a8,
                a32 = a16*a16, a64 = a32*a32, a128 = a64*a64,
                a256 = a128*a128, a512 = a256*a256,
                a1024 = a512*a512, a2048 = a1024*a1024;

    // a^(4*lane), exact via bit product
    float A4L = 1.0f;
    if (lane & 1)  A4L *= a4;
    if (lane & 2)  A4L *= a8;
    if (lane & 4)  A4L *= a16;
    if (lane & 8)  A4L *= a32;
    if (lane & 16) A4L *= a64;

    // ---- load: 4 coalesced float4 per thread, zero-pad tail ----
    float xv[16];
    #pragma unroll
    for (int j = 0; j < NSEG; j++) {
        int i = j * 1024 + tid * 4;
        float4 t4 = make_float4(0.f, 0.f, 0.f, 0.f);
        if (i < T_LEN) t4 = *reinterpret_cast<const float4*>(xr + i);
        xv[4*j+0] = t4.x; xv[4*j+1] = t4.y; xv[4*j+2] = t4.z; xv[4*j+3] = t4.w;
    }

    // ---- pass 1: serial 4-scan + 5-step constant-a Kogge-Stone per segment ----
    // b[0] = x[0] (global init), b[t] = S*x[t] otherwise
    float P[NSEG];     // inclusive per-lane scan value (zero warp carry-in)
    #pragma unroll
    for (int j = 0; j < NSEG; j++) {
        float h = 0.f;
        #pragma unroll
        for (int k = 0; k < 4; k++) {
            float b = S_ * xv[4*j+k];
            if (j == 0 && tid == 0 && k == 0) b = xv[0];
            h = fmaf(a, h, b);
        }
        float y = h, yp;
        yp = __shfl_up_sync(0xFFFFFFFFu, y, 1);  if (lane >= 1)  y = fmaf(a4,  yp, y);
        yp = __shfl_up_sync(0xFFFFFFFFu, y, 2);  if (lane >= 2)  y = fmaf(a8,  yp, y);
        yp = __shfl_up_sync(0xFFFFFFFFu, y, 4);  if (lane >= 4)  y = fmaf(a16, yp, y);
        yp = __shfl_up_sync(0xFFFFFFFFu, y, 8);  if (lane >= 8)  y = fmaf(a32, yp, y);
        yp = __shfl_up_sync(0xFFFFFFFFu, y, 16); if (lane >= 16) y = fmaf(a64, yp, y);
        P[j] = y;
        if (lane == 31) sT[j * 8 + warp] = y;   // warp-chunk (128 elems) total
    }
    __syncthreads();

    // ---- middle scan: 32 warp-chunks in chain order c = j*8 + w (A = a^128) ----
    if (warp == 0) {
        float y = sT[lane], yp;
        yp = __shfl_up_sync(0xFFFFFFFFu, y, 1);  if (lane >= 1)  y = fmaf(a128,  yp, y);
        yp = __shfl_up_sync(0xFFFFFFFFu, y, 2);  if (lane >= 2)  y = fmaf(a256,  yp, y);
        yp = __shfl_up_sync(0xFFFFFFFFu, y, 4);  if (lane >= 4)  y = fmaf(a512,  yp, y);
        yp = __shfl_up_sync(0xFFFFFFFFu, y, 8);  if (lane >= 8)  y = fmaf(a1024, yp, y);
        yp = __shfl_up_sync(0xFFFFFFFFu, y, 16); if (lane >= 16) y = fmaf(a2048, yp, y);
        float e = __shfl_up_sync(0xFFFFFFFFu, y, 1);
        sC[lane] = (lane == 0) ? 0.f : e;       // exclusive carry per chunk
    }
    __syncthreads();

    // ---- pass 2: apply carries, seeded serial recurrence + pointwise PCEN ----
    #pragma unroll
    for (int j = 0; j < NSEG; j++) {
        float Cw = sC[j * 8 + warp];                    // carry into this warp-chunk
        float E  = __shfl_up_sync(0xFFFFFFFFu, P[j], 1); // lane-exclusive prefix
        if (lane == 0) E = 0.f;
        float sm = fmaf(A4L, Cw, E);                    // smooth value just before chunk

        float r[4];
        #pragma unroll
        for (int k = 0; k < 4; k++) {
            float xk = xv[4*j+k];
            float b = S_ * xk;
            if (j == 0 && tid == 0 && k == 0) b = xk;
            sm = fmaf(a, sm, b);
            float p = fex2(NALPHA * flg2(sm + EPSf));   // (sm+eps)^-0.98
            r[k] = fsqrt_approx(fmaf(xk, p, DELTA)) - DR;
        }

        int i = j * 1024 + tid * 4;
        if (i < T_LEN)
            *reinterpret_cast<float4*>(orow + i) = make_float4(r[0], r[1], r[2], r[3]);
    }
}

extern "C" void kernel_launch(void* const* d_in, const int* in_sizes, int n_in,
                              void* d_out, int out_size)
{
    const float* x = (const float*)d_in[0];
    float* out = (float*)d_out;
    int rows = in_sizes[0] / T_LEN;   // 8192
    pcen_kernel<<<rows, THREADS>>>(x, out);
}